// round 4
// baseline (speedup 1.0000x reference)
#include <cuda_runtime.h>
#include <cuda_bf16.h>
#include <cstdint>

// GCN layer: out = segment_sum(val * x[col]) @ W^T + b
//  = b + segment_sum(val * (x @ W^T)[col])    (projection commutes with sum)
//
// K1: xW = x @ W^T via mma.sync tf32 m16n8k8 (fp32 accum).
// K2: SpMM, warp-per-node. Edge (col,val) loaded as int4/float4 (aligned),
//     4 independent row gathers in flight per iteration.

#define D 128
#define MAX_N 50000
#define SPAD 132            // 128 + 4 padding words -> conflict-free frag loads

__device__ float g_xW[MAX_N * D];

__device__ __forceinline__ float to_tf32(float f) {
    float r;
    asm("cvt.rna.tf32.f32 %0, %1;" : "=f"(r) : "f"(f));
    return r;
}

__device__ __forceinline__ void mma_tf32(float* d, const uint32_t* a, const uint32_t* b) {
    asm volatile(
        "mma.sync.aligned.m16n8k8.row.col.f32.tf32.tf32.f32 "
        "{%0,%1,%2,%3}, {%4,%5,%6,%7}, {%8,%9}, {%0,%1,%2,%3};"
        : "+f"(d[0]), "+f"(d[1]), "+f"(d[2]), "+f"(d[3])
        : "r"(a[0]), "r"(a[1]), "r"(a[2]), "r"(a[3]), "r"(b[0]), "r"(b[1]));
}

// ---------------------------------------------------------------------------
// K1: xW[i, o] = sum_k x[i,k] * W[o,k]
// 128x128 tile per CTA, 256 threads = 8 warps (4x2), warp tile 32x64.
// ---------------------------------------------------------------------------
__global__ __launch_bounds__(256, 1)
void gemm_xw_mma(const float* __restrict__ x, const float* __restrict__ W, int N) {
    extern __shared__ float smem[];
    float* As = smem;                 // [128][SPAD]
    float* Ws = smem + 128 * SPAD;    // [128][SPAD]

    const int tid = threadIdx.x;
    const int block_row = blockIdx.x * 128;

    #pragma unroll
    for (int it = 0; it < 16; it++) {
        const int slot = tid + it * 256;        // float4 slot, 4096 total
        const int r = slot >> 5;
        const int c = (slot & 31) * 4;
        const int gr = block_row + r;
        float4 v = make_float4(0.f, 0.f, 0.f, 0.f);
        if (gr < N) v = *reinterpret_cast<const float4*>(x + (size_t)gr * D + c);
        float* dst = As + r * SPAD + c;
        dst[0] = to_tf32(v.x); dst[1] = to_tf32(v.y);
        dst[2] = to_tf32(v.z); dst[3] = to_tf32(v.w);
    }
    #pragma unroll
    for (int it = 0; it < 16; it++) {
        const int slot = tid + it * 256;
        const int r = slot >> 5;
        const int c = (slot & 31) * 4;
        float4 v = *reinterpret_cast<const float4*>(W + (size_t)r * D + c);
        float* dst = Ws + r * SPAD + c;
        dst[0] = to_tf32(v.x); dst[1] = to_tf32(v.y);
        dst[2] = to_tf32(v.z); dst[3] = to_tf32(v.w);
    }
    __syncthreads();

    const uint32_t* Ab = reinterpret_cast<const uint32_t*>(As);
    const uint32_t* Wb = reinterpret_cast<const uint32_t*>(Ws);

    const int wid  = tid >> 5;
    const int lane = tid & 31;
    const int grp  = lane >> 2;       // 0..7
    const int tig  = lane & 3;        // 0..3
    const int warpRow = (wid & 3) * 32;
    const int warpCol = (wid >> 2) * 64;

    float acc[2][8][4];
    #pragma unroll
    for (int mt = 0; mt < 2; mt++)
        #pragma unroll
        for (int nt = 0; nt < 8; nt++)
            #pragma unroll
            for (int q = 0; q < 4; q++) acc[mt][nt][q] = 0.f;

    #pragma unroll
    for (int ks = 0; ks < 16; ks++) {
        const int k0 = ks * 8;
        uint32_t a[2][4];
        #pragma unroll
        for (int mt = 0; mt < 2; mt++) {
            const int r0 = warpRow + mt * 16 + grp;
            a[mt][0] = Ab[r0 * SPAD + k0 + tig];
            a[mt][1] = Ab[(r0 + 8) * SPAD + k0 + tig];
            a[mt][2] = Ab[r0 * SPAD + k0 + tig + 4];
            a[mt][3] = Ab[(r0 + 8) * SPAD + k0 + tig + 4];
        }
        uint32_t b[8][2];
        #pragma unroll
        for (int nt = 0; nt < 8; nt++) {
            const int n0 = warpCol + nt * 8 + grp;
            b[nt][0] = Wb[n0 * SPAD + k0 + tig];
            b[nt][1] = Wb[n0 * SPAD + k0 + tig + 4];
        }
        #pragma unroll
        for (int mt = 0; mt < 2; mt++)
            #pragma unroll
            for (int nt = 0; nt < 8; nt++)
                mma_tf32(acc[mt][nt], a[mt], b[nt]);
    }

    #pragma unroll
    for (int mt = 0; mt < 2; mt++) {
        const int r0 = block_row + warpRow + mt * 16 + grp;
        #pragma unroll
        for (int nt = 0; nt < 8; nt++) {
            const int c0 = warpCol + nt * 8 + tig * 2;
            if (r0 < N)
                *reinterpret_cast<float2*>(g_xW + (size_t)r0 * D + c0) =
                    make_float2(acc[mt][nt][0], acc[mt][nt][1]);
            if (r0 + 8 < N)
                *reinterpret_cast<float2*>(g_xW + (size_t)(r0 + 8) * D + c0) =
                    make_float2(acc[mt][nt][2], acc[mt][nt][3]);
        }
    }
}

// ---------------------------------------------------------------------------
// K2: out[i] = b + sum_{e in [rp(i), rp(i+1))} val[e] * xW[col[e]]
// rp(j) = lower_bound(edge_row, j), computed by lanes 0/1 + shfl.
// Main loop: int4/float4 edge loads (e aligned to 4), 4 gathers in flight.
// ---------------------------------------------------------------------------
__device__ __forceinline__ void acc_edge(float4& acc, int col, float v, int lane) {
    float4 a = *reinterpret_cast<const float4*>(g_xW + (size_t)col * D + lane * 4);
    acc.x = fmaf(v, a.x, acc.x); acc.y = fmaf(v, a.y, acc.y);
    acc.z = fmaf(v, a.z, acc.z); acc.w = fmaf(v, a.w, acc.w);
}

__global__ __launch_bounds__(256)
void spmm_kernel(const int* __restrict__ erow, const int* __restrict__ ecol,
                 const float* __restrict__ eval, const float* __restrict__ b,
                 float* __restrict__ out, int N, int E) {
    const int warp = (blockIdx.x * blockDim.x + threadIdx.x) >> 5;
    const int lane = threadIdx.x & 31;
    if (warp >= N) return;

    int bound = 0;
    if (lane < 2) {
        const int tgt = warp + lane;   // lower_bound target
        int lo = 0, hi = E;
        while (lo < hi) {
            int mid = (lo + hi) >> 1;
            if (__ldg(erow + mid) < tgt) lo = mid + 1; else hi = mid;
        }
        bound = lo;
    }
    const int start = __shfl_sync(0xFFFFFFFFu, bound, 0);
    const int end   = __shfl_sync(0xFFFFFFFFu, bound, 1);

    float4 acc = *reinterpret_cast<const float4*>(b + lane * 4);

    int e = start;
    // peel to 4-alignment
    while (e < end && (e & 3)) {
        acc_edge(acc, __ldg(ecol + e), __ldg(eval + e), lane);
        e++;
    }
    // main: 4 edges per iteration, vector metadata loads, 4 gathers in flight
    for (; e + 4 <= end; e += 4) {
        int4   c = __ldg(reinterpret_cast<const int4*>(ecol + e));
        float4 v = __ldg(reinterpret_cast<const float4*>(eval + e));
        const float* p0 = g_xW + (size_t)c.x * D + lane * 4;
        const float* p1 = g_xW + (size_t)c.y * D + lane * 4;
        const float* p2 = g_xW + (size_t)c.z * D + lane * 4;
        const float* p3 = g_xW + (size_t)c.w * D + lane * 4;
        float4 a0 = *reinterpret_cast<const float4*>(p0);
        float4 a1 = *reinterpret_cast<const float4*>(p1);
        float4 a2 = *reinterpret_cast<const float4*>(p2);
        float4 a3 = *reinterpret_cast<const float4*>(p3);
        acc.x = fmaf(v.x, a0.x, acc.x); acc.y = fmaf(v.x, a0.y, acc.y);
        acc.z = fmaf(v.x, a0.z, acc.z); acc.w = fmaf(v.x, a0.w, acc.w);
        acc.x = fmaf(v.y, a1.x, acc.x); acc.y = fmaf(v.y, a1.y, acc.y);
        acc.z = fmaf(v.y, a1.z, acc.z); acc.w = fmaf(v.y, a1.w, acc.w);
        acc.x = fmaf(v.z, a2.x, acc.x); acc.y = fmaf(v.z, a2.y, acc.y);
        acc.z = fmaf(v.z, a2.z, acc.z); acc.w = fmaf(v.z, a2.w, acc.w);
        acc.x = fmaf(v.w, a3.x, acc.x); acc.y = fmaf(v.w, a3.y, acc.y);
        acc.z = fmaf(v.w, a3.z, acc.z); acc.w = fmaf(v.w, a3.w, acc.w);
    }
    // tail
    while (e < end) {
        acc_edge(acc, __ldg(ecol + e), __ldg(eval + e), lane);
        e++;
    }

    *reinterpret_cast<float4*>(out + (size_t)warp * D + lane * 4) = acc;
}

// ---------------------------------------------------------------------------
extern "C" void kernel_launch(void* const* d_in, const int* in_sizes, int n_in,
                              void* d_out, int out_size) {
    const float* x    = (const float*)d_in[0];
    const int*   erow = (const int*)  d_in[1];
    const int*   ecol = (const int*)  d_in[2];
    const float* eval = (const float*)d_in[3];
    const float* W    = (const float*)d_in[4];
    const float* b    = (const float*)d_in[5];

    const int N = in_sizes[0] / D;
    const int E = in_sizes[1];

    const int smem_bytes = 2 * 128 * SPAD * sizeof(float);   // ~135 KB
    cudaFuncSetAttribute(gemm_xw_mma, cudaFuncAttributeMaxDynamicSharedMemorySize, smem_bytes);

    gemm_xw_mma<<<(N + 127) / 128, 256, smem_bytes>>>(x, W, N);

    const int warps_per_block = 8;
    spmm_kernel<<<(N + warps_per_block - 1) / warps_per_block, warps_per_block * 32>>>(
        erow, ecol, eval, b, (float*)d_out, N, E);
}